// round 1
// baseline (speedup 1.0000x reference)
#include <cuda_runtime.h>

#define RES     256
#define MASKN   128
#define CHOUT   16
#define RR      8
#define NCH     128          // CH*RR phasor channels per plane
#define CPB     8            // FFT channels per block
#define NPTS    262144
#define PI_F    3.14159265358979323846f

// Scratch (device globals: allocation-free rule)
__device__ float2 g_mid[MASKN * RES * NCH];        // [ky<128][x][ch]  complex, 33.5 MB
__device__ float  g_feat[RES * RES * 2 * NCH];     // [y][x][ch256]    67 MB

// ---------------------------------------------------------------------------
// Shared-memory Stockham radix-2 inverse FFT, 256 points, CPB channels.
// Twiddle table tw[j] = exp(+i*pi*j/128). Result ends in A (8 swaps).
// ---------------------------------------------------------------------------
__device__ __forceinline__ void ifft256_block(float2 (*A)[256], float2 (*B)[256],
                                              const float2* tw) {
    int tid = threadIdx.x;
    float2 (*src)[256] = A;
    float2 (*dst)[256] = B;
#pragma unroll
    for (int st = 0; st < 8; st++) {
        __syncthreads();
        int ns = 1 << st;
#pragma unroll
        for (int k = 0; k < (CPB * 128) / 256; k++) {
            int idx = tid + k * 256;
            int cc = idx >> 7;
            int j  = idx & 127;
            int jm = j & (ns - 1);
            float2 v0 = src[cc][j];
            float2 v1 = src[cc][j + 128];
            float2 w  = tw[jm << (7 - st)];
            float2 t  = make_float2(w.x * v1.x - w.y * v1.y,
                                    w.x * v1.y + w.y * v1.x);
            int o = ((j >> st) << (st + 1)) | jm;
            dst[cc][o]      = make_float2(v0.x + t.x, v0.y + t.y);
            dst[cc][o + ns] = make_float2(v0.x - t.x, v0.y - t.y);
        }
        float2 (*tmp)[256] = src; src = dst; dst = tmp;
    }
    __syncthreads();
}

// ---------------------------------------------------------------------------
// Kernel A: x-direction IFFT for the 128 nonzero rows (ky < 128).
// grid = (NCH/CPB, 128), block = 256.
// ---------------------------------------------------------------------------
__global__ void kfftx(const float* __restrict__ P) {
    __shared__ float2 sA[CPB][256];
    __shared__ float2 sB[CPB][256];
    __shared__ float2 tw[128];
    int tid = threadIdx.x;
    int g   = blockIdx.x;
    int ky  = blockIdx.y;

    if (tid < 128) {
        float sn, cs;
        sincosf(PI_F * (float)tid / 128.f, &sn, &cs);
        tw[tid] = make_float2(cs, sn);          // inverse: +i sign
    }
    const float2* Pf = (const float2*)P;
    for (int idx = tid; idx < CPB * 128; idx += 256) {
        int cc = idx >> 7;
        int kx = idx & 127;
        int ch = g * CPB + cc;
        sA[cc][kx]       = Pf[(ch * 256 + ky) * 256 + kx];   // masked low freqs
        sA[cc][kx + 128] = make_float2(0.f, 0.f);            // zero pad
    }
    ifft256_block(sA, sB, tw);
    for (int idx = tid; idx < CPB * 256; idx += 256) {
        int cc = idx & (CPB - 1);
        int x  = idx >> 3;
        g_mid[(ky * 256 + x) * NCH + g * CPB + cc] = sA[cc][x];
    }
}

// ---------------------------------------------------------------------------
// Kernel B: y-direction IFFT, write texel-major feat with 1/65536 norm.
// grid = (NCH/CPB, 256), block = 256.
// ---------------------------------------------------------------------------
__global__ void kffty() {
    __shared__ float2 sA[CPB][256];
    __shared__ float2 sB[CPB][256];
    __shared__ float2 tw[128];
    int tid = threadIdx.x;
    int g   = blockIdx.x;
    int x   = blockIdx.y;

    if (tid < 128) {
        float sn, cs;
        sincosf(PI_F * (float)tid / 128.f, &sn, &cs);
        tw[tid] = make_float2(cs, sn);
    }
    for (int idx = tid; idx < CPB * 128; idx += 256) {
        int cc = idx & (CPB - 1);
        int ky = idx >> 3;
        sA[cc][ky]       = g_mid[(ky * 256 + x) * NCH + g * CPB + cc];
        sA[cc][ky + 128] = make_float2(0.f, 0.f);
    }
    ifft256_block(sA, sB, tw);
    const float scale = 1.f / 65536.f;          // ifft2 normalization
    for (int idx = tid; idx < CPB * 256; idx += 256) {
        int cc = idx & (CPB - 1);
        int y  = idx >> 3;
        int ch = g * CPB + cc;
        float2 v = sA[cc][y];
        // feat channel 2*ch = real, 2*ch+1 = imag (stack axis=1 -> interleaved)
        float2* fo = (float2*)&g_feat[(((y << 8) + x) << 8) + 2 * ch];
        *fo = make_float2(v.x * scale, v.y * scale);
    }
}

// ---------------------------------------------------------------------------
// Sampling: one warp per point. Lane t owns feat channels [8t, 8t+8).
// Lanes 0..15 -> real block (cos), lanes 16..31 -> imag block (-sin).
// grid = NPTS/8, block = 256.
// ---------------------------------------------------------------------------
__global__ void ksample(const float* __restrict__ inputs, float* __restrict__ out,
                        int ix, int iy, int is, int accum) {
    int warp = (blockIdx.x * blockDim.x + threadIdx.x) >> 5;
    int lane = threadIdx.x & 31;
    if (warp >= NPTS) return;

    float gx = __ldg(inputs + warp * 3 + ix);
    float gy = __ldg(inputs + warp * 3 + iy);
    float ic = __ldg(inputs + warp * 3 + is);

    float x = (gx + 1.f) * 127.5f;
    float y = (gy + 1.f) * 127.5f;
    float xf = floorf(x), yf = floorf(y);
    float wx = x - xf,    wy = y - yf;
    int x0 = min(max((int)xf, 0), 255);
    int x1 = min(x0 + 1, 255);
    int y0 = min(max((int)yf, 0), 255);
    int y1 = min(y0 + 1, 255);
    float w00 = (1.f - wx) * (1.f - wy);
    float w01 = wx * (1.f - wy);
    float w10 = (1.f - wx) * wy;
    float w11 = wx * wy;

    int co = lane << 3;                          // channel offset for this lane
    const float* b00 = g_feat + ((((y0 << 8) + x0) << 8) + co);
    const float* b01 = g_feat + ((((y0 << 8) + x1) << 8) + co);
    const float* b10 = g_feat + ((((y1 << 8) + x0) << 8) + co);
    const float* b11 = g_feat + ((((y1 << 8) + x1) << 8) + co);

    float4 a0 = *(const float4*)(b00);
    float4 a1 = *(const float4*)(b00 + 4);
    float4 c0 = *(const float4*)(b01);
    float4 c1 = *(const float4*)(b01 + 4);
    float4 d0 = *(const float4*)(b10);
    float4 d1 = *(const float4*)(b10 + 4);
    float4 e0 = *(const float4*)(b11);
    float4 e1 = *(const float4*)(b11 + 4);

    float F[8];
    F[0] = w00 * a0.x + w01 * c0.x + w10 * d0.x + w11 * e0.x;
    F[1] = w00 * a0.y + w01 * c0.y + w10 * d0.y + w11 * e0.y;
    F[2] = w00 * a0.z + w01 * c0.z + w10 * d0.z + w11 * e0.z;
    F[3] = w00 * a0.w + w01 * c0.w + w10 * d0.w + w11 * e0.w;
    F[4] = w00 * a1.x + w01 * c1.x + w10 * d1.x + w11 * e1.x;
    F[5] = w00 * a1.y + w01 * c1.y + w10 * d1.y + w11 * e1.y;
    F[6] = w00 * a1.z + w01 * c1.z + w10 * d1.z + w11 * e1.z;
    F[7] = w00 * a1.w + w01 * c1.w + w10 * d1.w + w11 * e1.w;

    float s = (ic + 1.f) * 127.5f;
    float val = 0.f;
#pragma unroll
    for (int r = 0; r < 8; r++) {
        float coef = (float)((1 << r) - 1);
        float ang  = s * coef * (PI_F / 128.f);
        float c, sn;
        sincosf(ang, &sn, &c);
        val = fmaf(F[r], (lane < 16) ? c : -sn, val);
    }
    val += __shfl_down_sync(0xffffffffu, val, 16);
    if (lane < 16) {
        float* o = out + warp * CHOUT + lane;
        if (accum) *o += val; else *o = val;
    }
}

// ---------------------------------------------------------------------------
extern "C" void kernel_launch(void* const* d_in, const int* in_sizes, int n_in,
                              void* d_out, int out_size) {
    const float* inp = (const float*)d_in[3];
    float* out = (float*)d_out;
    // Plane coordinate permutations: (gx, gy, s) index into inputs[:,3]
    const int sel[3][3] = { {1, 2, 0},   // Pu: gx=in1, gy=in2, s=in0
                            {0, 2, 1},   // Pv: gx=in0, gy=in2, s=in1
                            {0, 1, 2} }; // Pw: gx=in0, gy=in1, s=in2
    for (int p = 0; p < 3; p++) {
        const float* P = (const float*)d_in[p];
        kfftx<<<dim3(NCH / CPB, MASKN), 256>>>(P);
        kffty<<<dim3(NCH / CPB, RES), 256>>>();
        ksample<<<NPTS / 8, 256>>>(inp, out, sel[p][0], sel[p][1], sel[p][2], p > 0);
    }
}

// round 2
// speedup vs baseline: 1.8123x; 1.8123x over previous
#include <cuda_runtime.h>
#include <cuda_fp16.h>

#define RES     256
#define CHOUT   16
#define NCH     128          // CH*RR phasor channels per plane
#define CPB     8            // FFT channels per block
#define NPTS    262144
#define PI_F    3.14159265358979323846f

// Scratch (device globals: allocation-free rule)
__device__ float2 g_mid[128 * 256 * NCH];          // [ky<128][x][ch] complex fp32, 33.5 MB
__device__ __half g_feat[RES * RES * 2 * NCH];     // [y][x][256ch] fp16 (unnormalized), 33.5 MB

__device__ __forceinline__ float2 cadd(float2 a, float2 b) { return make_float2(a.x + b.x, a.y + b.y); }
__device__ __forceinline__ float2 csub(float2 a, float2 b) { return make_float2(a.x - b.x, a.y - b.y); }
__device__ __forceinline__ float2 cmul(float2 a, float2 b) {
    return make_float2(fmaf(a.x, b.x, -a.y * b.y), fmaf(a.x, b.y, a.y * b.x));
}
__device__ __forceinline__ float2 muli(float2 a) { return make_float2(-a.y, a.x); }

// Bank-conflict swizzle: pure relabeling of smem element index (bijection on [0,256)).
__device__ __forceinline__ int sz(int e) { return e ^ (((e >> 4) & 3) << 2); }

// ---------------------------------------------------------------------------
// Generic radix-4 Stockham stage (inverse: +i), NS in {4,16,64}.
// Verified: composes to X[n] = sum_k x[k] exp(+2*pi*i*n*k/256) with natural order.
// ---------------------------------------------------------------------------
template<int NS>
__device__ __forceinline__ void stage4(float2 (*src)[257], float2 (*dst)[257],
                                       const float2* tw) {
    __syncthreads();
    int tid = threadIdx.x;
#pragma unroll
    for (int k = 0; k < 2; k++) {
        int idx = tid + (k << 8);
        int cc = idx >> 6, j = idx & 63;
        int jm = j & (NS - 1);
        float2 v0 = src[cc][sz(j)];
        float2 v1 = src[cc][sz(j + 64)];
        float2 v2 = src[cc][sz(j + 128)];
        float2 v3 = src[cc][sz(j + 192)];
        const int MS = 64 / NS;                 // tw[m] = exp(+2*pi*i*m/256)
        float2 w1 = tw[jm * MS];
        float2 w2 = tw[2 * jm * MS];
        float2 w3 = tw[3 * jm * MS];
        v1 = cmul(v1, w1); v2 = cmul(v2, w2); v3 = cmul(v3, w3);
        float2 a = cadd(v0, v2), b = csub(v0, v2);
        float2 c = cadd(v1, v3), d = muli(csub(v1, v3));
        int o = ((j & ~(NS - 1)) << 2) | jm;
        dst[cc][sz(o)]          = cadd(a, c);
        dst[cc][sz(o + NS)]     = cadd(b, d);
        dst[cc][sz(o + 2 * NS)] = csub(a, c);
        dst[cc][sz(o + 3 * NS)] = csub(b, d);
    }
}

// ---------------------------------------------------------------------------
// Kernel A: x-direction IFFT for the 128 nonzero rows. Stage 0 (ns=1) is
// specialized for the zero-padded top half (v2=v3=0) and reads gmem directly.
// grid = (NCH/CPB, 128), block = 256.
// ---------------------------------------------------------------------------
__global__ void kfftx(const float* __restrict__ P) {
    __shared__ float2 sA[CPB][257];
    __shared__ float2 sB[CPB][257];
    __shared__ float2 tw[256];
    int tid = threadIdx.x, g = blockIdx.x, ky = blockIdx.y;
    {
        float sn, cs;
        sincosf(PI_F * (float)tid / 128.f, &sn, &cs);
        tw[tid] = make_float2(cs, sn);          // inverse: +i
    }
    const float2* Pf = (const float2*)P;
#pragma unroll
    for (int k = 0; k < 2; k++) {
        int idx = tid + (k << 8);
        int cc = idx >> 6, j = idx & 63;        // coalesced on kx
        int ch = g * CPB + cc;
        const float2* row = Pf + ((size_t)ch * 256 + ky) * 256;
        float2 v0 = row[j], v1 = row[j + 64];   // both in nonzero region (<128)
        sA[cc][sz(4 * j)]     = cadd(v0, v1);
        sA[cc][sz(4 * j + 1)] = cadd(v0, muli(v1));
        sA[cc][sz(4 * j + 2)] = csub(v0, v1);
        sA[cc][sz(4 * j + 3)] = csub(v0, muli(v1));
    }
    stage4<4>(sA, sB, tw);
    stage4<16>(sB, sA, tw);
    stage4<64>(sA, sB, tw);
    __syncthreads();
    for (int idx = tid; idx < CPB * 256; idx += 256) {
        int cc = idx & 7, x = idx >> 3;
        g_mid[((size_t)ky * 256 + x) * NCH + g * CPB + cc] = sB[cc][sz(x)];
    }
}

// ---------------------------------------------------------------------------
// Kernel B: y-direction IFFT (rows ky>=128 are zero), writes texel-major fp16
// feat WITHOUT the 1/65536 normalization (applied in ksample).
// grid = (NCH/CPB, 256), block = 256.
// ---------------------------------------------------------------------------
__global__ void kffty() {
    __shared__ float2 sA[CPB][257];
    __shared__ float2 sB[CPB][257];
    __shared__ float2 tw[256];
    int tid = threadIdx.x, g = blockIdx.x, x = blockIdx.y;
    {
        float sn, cs;
        sincosf(PI_F * (float)tid / 128.f, &sn, &cs);
        tw[tid] = make_float2(cs, sn);
    }
#pragma unroll
    for (int k = 0; k < 2; k++) {
        int idx = tid + (k << 8);
        int cc = idx & 7, j = idx >> 3;         // coalesced on ch (64B chunks)
        int ch = g * CPB + cc;
        float2 v0 = g_mid[((size_t)j * 256 + x) * NCH + ch];
        float2 v1 = g_mid[((size_t)(j + 64) * 256 + x) * NCH + ch];
        sA[cc][sz(4 * j)]     = cadd(v0, v1);
        sA[cc][sz(4 * j + 1)] = cadd(v0, muli(v1));
        sA[cc][sz(4 * j + 2)] = csub(v0, v1);
        sA[cc][sz(4 * j + 3)] = csub(v0, muli(v1));
    }
    stage4<4>(sA, sB, tw);
    stage4<16>(sB, sA, tw);
    stage4<64>(sA, sB, tw);
    __syncthreads();
    for (int idx = tid; idx < CPB * 256; idx += 256) {
        int cc = idx & 7, y = idx >> 3;
        int ch = g * CPB + cc;
        float2 v = sB[cc][sz(y)];
        __half2* fo = (__half2*)&g_feat[(((y << 8) + x) << 8) + 2 * ch];
        *fo = __floats2half2_rn(v.x, v.y);      // ch*2 = real, ch*2+1 = imag
    }
}

// ---------------------------------------------------------------------------
// Sampling: one warp per point. Lane t owns feat channels [8t, 8t+8).
// Lanes 0..15 -> real block (cos theta_r), lanes 16..31 -> imag block (-sin).
// Fourier phases via squaring recurrence: theta_{r+1} = 2*theta_r + theta_1.
// grid = NPTS/8, block = 256.
// ---------------------------------------------------------------------------
__device__ __forceinline__ void ld8h(const __half* p, float* f) {
    uint4 u = *(const uint4*)p;                 // 8 halves = 16B, aligned
    const half2* h = (const half2*)&u;
    float2 a = __half22float2(h[0]);
    float2 b = __half22float2(h[1]);
    float2 c = __half22float2(h[2]);
    float2 d = __half22float2(h[3]);
    f[0] = a.x; f[1] = a.y; f[2] = b.x; f[3] = b.y;
    f[4] = c.x; f[5] = c.y; f[6] = d.x; f[7] = d.y;
}

__global__ void ksample(const float* __restrict__ inputs, float* __restrict__ out,
                        int ix, int iy, int is, int accum) {
    int warp = (blockIdx.x * blockDim.x + threadIdx.x) >> 5;
    int lane = threadIdx.x & 31;
    if (warp >= NPTS) return;

    float gx = __ldg(inputs + warp * 3 + ix);
    float gy = __ldg(inputs + warp * 3 + iy);
    float ic = __ldg(inputs + warp * 3 + is);

    float xx = (gx + 1.f) * 127.5f;
    float yy = (gy + 1.f) * 127.5f;
    float xf = floorf(xx), yf = floorf(yy);
    float wx = xx - xf, wy = yy - yf;
    int x0 = min(max((int)xf, 0), 255);
    int x1 = min(x0 + 1, 255);
    int y0 = min(max((int)yf, 0), 255);
    int y1 = min(y0 + 1, 255);
    float w00 = (1.f - wx) * (1.f - wy);
    float w01 = wx * (1.f - wy);
    float w10 = (1.f - wx) * wy;
    float w11 = wx * wy;

    int co = lane << 3;
    float F[8], t[8];
    ld8h(g_feat + ((((y0 << 8) + x0) << 8) + co), t);
#pragma unroll
    for (int i = 0; i < 8; i++) F[i] = w00 * t[i];
    ld8h(g_feat + ((((y0 << 8) + x1) << 8) + co), t);
#pragma unroll
    for (int i = 0; i < 8; i++) F[i] = fmaf(w01, t[i], F[i]);
    ld8h(g_feat + ((((y1 << 8) + x0) << 8) + co), t);
#pragma unroll
    for (int i = 0; i < 8; i++) F[i] = fmaf(w10, t[i], F[i]);
    ld8h(g_feat + ((((y1 << 8) + x1) << 8) + co), t);
#pragma unroll
    for (int i = 0; i < 8; i++) F[i] = fmaf(w11, t[i], F[i]);

    float s = (ic + 1.f) * 127.5f;
    float2 e1;
    sincosf(s * (PI_F / 128.f), &e1.y, &e1.x);  // theta_1 = pi*s/128
    bool re = (lane < 16);
    float val = re ? F[0] : 0.f;                // r=0: coef=0 -> cos=1, sin=0
    float2 u = e1;                              // angle theta_1*(2^1-1)
#pragma unroll
    for (int r = 1; r < 8; r++) {
        val = fmaf(F[r], re ? u.x : -u.y, val);
        if (r < 7) u = cmul(cmul(u, u), e1);    // 2*theta + theta_1
    }
    val += __shfl_down_sync(0xffffffffu, val, 16);
    if (lane < 16) {
        float v = val * (1.f / 65536.f);        // deferred ifft2 normalization
        float* o = out + warp * CHOUT + lane;
        if (accum) *o += v; else *o = v;
    }
}

// ---------------------------------------------------------------------------
extern "C" void kernel_launch(void* const* d_in, const int* in_sizes, int n_in,
                              void* d_out, int out_size) {
    const float* inp = (const float*)d_in[3];
    float* out = (float*)d_out;
    // Plane coordinate permutations: (gx, gy, s) indices into inputs[:,3]
    const int sel[3][3] = { {1, 2, 0},   // Pu
                            {0, 2, 1},   // Pv
                            {0, 1, 2} }; // Pw
    for (int p = 0; p < 3; p++) {
        const float* P = (const float*)d_in[p];
        kfftx<<<dim3(NCH / CPB, 128), 256>>>(P);
        kffty<<<dim3(NCH / CPB, RES), 256>>>();
        ksample<<<NPTS / 8, 256>>>(inp, out, sel[p][0], sel[p][1], sel[p][2], p > 0);
    }
}